// round 8
// baseline (speedup 1.0000x reference)
#include <cuda_runtime.h>
#include <cuda_bf16.h>
#include <mma.h>
#include <stdint.h>

using namespace nvcuda;

#define NN  50000
#define EE  800000
#define NBLK 196            // ceil(NN/256)
#define NPAD (NN + 128)     // row padding so wmma stores in the last CTA stay in-bounds

// ---------------- scratch (device globals) ----------------------------------
__device__ __align__(16) float g_t[NPAD * 128];
__device__ __align__(16) float g_r[NPAD * 128];
__device__ __align__(16) float g_h[NPAD * 128];
__device__ int   g_degc[NN];
__device__ int   g_rowoff[NN + 1];
__device__ int   g_wptr[NN];
__device__ int   g_csr[EE];
__device__ float g_invdeg[NN];
__device__ int   g_bsum[NBLK];
__device__ int   g_bpre[NBLK];

// ---------------- edge dtype probe ------------------------------------------
__device__ __forceinline__ int probe_is64(const void* ei) {
    int lane = threadIdx.x & 31;
    long long v = ((const long long*)ei)[lane];
    unsigned ok = __ballot_sync(0xffffffffu, v >= 0 && v < NN);
    return ok == 0xffffffffu;
}

__device__ __forceinline__ void load_edge(const void* ei, int e, int is64,
                                          int& s, int& d) {
    if (is64) {
        const long long* p = (const long long*)ei;
        s = (int)p[e];
        d = (int)p[EE + e];
    } else {
        const int* p = (const int*)ei;
        s = p[e];
        d = p[EE + e];
    }
    s = min(max(s, 0), NN - 1);
    d = min(max(d, 0), NN - 1);
}

// ---------------- graph preprocessing ---------------------------------------
__global__ void count_deg_kernel(const void* __restrict__ ei) {
    int is64 = probe_is64(ei);
    int e = blockIdx.x * blockDim.x + threadIdx.x;
    if (e < EE) {
        int s, d;
        load_edge(ei, e, is64, s, d);
        atomicAdd(&g_degc[d], 1);
    }
}

__global__ void blocksum_kernel() {
    int i = blockIdx.x * 256 + threadIdx.x;
    int v = (i < NN) ? g_degc[i] : 0;
#pragma unroll
    for (int off = 16; off > 0; off >>= 1)
        v += __shfl_down_sync(0xffffffffu, v, off);
    __shared__ int ws[8];
    if ((threadIdx.x & 31) == 0) ws[threadIdx.x >> 5] = v;
    __syncthreads();
    if (threadIdx.x == 0) {
        int s = 0;
#pragma unroll
        for (int w = 0; w < 8; w++) s += ws[w];
        g_bsum[blockIdx.x] = s;
    }
}

__global__ void scan_bsum_kernel() {
    __shared__ int sh[256];
    int t = threadIdx.x;
    int v = (t < NBLK) ? g_bsum[t] : 0;
    sh[t] = v;
    __syncthreads();
#pragma unroll
    for (int off = 1; off < 256; off <<= 1) {
        int u = (t >= off) ? sh[t - off] : 0;
        __syncthreads();
        sh[t] += u;
        __syncthreads();
    }
    if (t < NBLK) g_bpre[t] = sh[t] - v;
    if (t == NBLK - 1) g_rowoff[NN] = sh[t];
}

__global__ void write_off_kernel() {
    __shared__ int sh[256];
    int t = threadIdx.x;
    int i = blockIdx.x * 256 + t;
    int v = (i < NN) ? g_degc[i] : 0;
    sh[t] = v;
    __syncthreads();
#pragma unroll
    for (int off = 1; off < 256; off <<= 1) {
        int u = (t >= off) ? sh[t - off] : 0;
        __syncthreads();
        sh[t] += u;
        __syncthreads();
    }
    if (i < NN) {
        int excl = g_bpre[blockIdx.x] + sh[t] - v;
        g_rowoff[i] = excl;
        g_wptr[i]   = excl;
        g_invdeg[i] = 1.0f / fmaxf((float)v, 1.0f);
        g_degc[i]   = 0;
    }
}

__global__ void fill_csr_kernel(const void* __restrict__ ei) {
    int is64 = probe_is64(ei);
    int e = blockIdx.x * blockDim.x + threadIdx.x;
    if (e < EE) {
        int s, d;
        load_edge(ei, e, is64, s, d);
        int p = atomicAdd(&g_wptr[d], 1);
        if (p >= 0 && p < EE) g_csr[p] = s;
    }
}

// ---------------- fused dual wmma GEMM: t = A@Wl AND r = A@Wr ---------------
// One CTA (512 threads, 16 warps in 4m x 4n) computes 128 rows x (Wl||Wr).
// A is staged + bf16-hi/lo split ONCE for both outputs (vs twice before).
// 3-term split MMA: Ahi*Whi + Ahi*Wlo + Alo*Whi, fp32 accumulators.
#define KCH 16
#define KP  24     // A smem stride (elems)

template <int COLT>   // 128 or 64; concatenated width = 2*COLT
__global__ __launch_bounds__(512)
void gemm_wmma_kernel(const float* __restrict__ A,
                      const float* __restrict__ Wl,
                      const float* __restrict__ Wr) {
    constexpr int WTOT = 2 * COLT;        // 256 or 128
    constexpr int CP = WTOT + 8;          // W smem stride
    constexpr int WN = WTOT / 4;          // cols per n-warp (64 or 32)
    constexpr int NF = WN / 16;           // frags per warp (4 or 2)

    __shared__ __align__(32) __nv_bfloat16 Ahi[128 * KP];
    __shared__ __align__(32) __nv_bfloat16 Alo[128 * KP];
    __shared__ __align__(32) __nv_bfloat16 Whi[KCH * CP];
    __shared__ __align__(32) __nv_bfloat16 Wlo[KCH * CP];

    const float* Ap = A ? A : g_h;

    const int tid = threadIdx.x;
    const int wid = tid >> 5;
    const int wm = wid & 3;           // m-tile 0..3 (32 rows each)
    const int wn = wid >> 2;          // n-tile 0..3 (WN cols each)
    const int rowBase = blockIdx.x * 128;

    wmma::fragment<wmma::accumulator, 16, 16, 16, float> acc[2][NF];
#pragma unroll
    for (int m = 0; m < 2; m++)
#pragma unroll
        for (int f = 0; f < NF; f++) wmma::fill_fragment(acc[m][f], 0.0f);

    const int arow = tid >> 2;            // 0..127
    const int akq  = (tid & 3) * 4;       // k offset 0,4,8,12

    for (int kc = 0; kc < 128; kc += KCH) {
        // ---- stage A chunk: 128 rows x 16 k, fp32 -> hi/lo bf16 (once) ----
        {
            int grow = rowBase + arow;
            float4 v = make_float4(0.f, 0.f, 0.f, 0.f);
            if (grow < NN)
                v = *(const float4*)(Ap + (size_t)grow * 128 + kc + akq);
            float vs[4] = {v.x, v.y, v.z, v.w};
            __nv_bfloat16* dh = Ahi + arow * KP + akq;
            __nv_bfloat16* dl = Alo + arow * KP + akq;
#pragma unroll
            for (int e = 0; e < 4; e++) {
                __nv_bfloat16 h = __float2bfloat16(vs[e]);
                __nv_bfloat16 l = __float2bfloat16(vs[e] - __bfloat162float(h));
                dh[e] = h;
                dl[e] = l;
            }
        }
        // ---- stage W chunk: 16 k x (Wl||Wr) ----
#pragma unroll
        for (int f = tid; f < KCH * WTOT; f += 512) {
            int k = f / WTOT, n = f % WTOT;
            float w = (n < COLT) ? Wl[(size_t)(kc + k) * COLT + n]
                                 : Wr[(size_t)(kc + k) * COLT + (n - COLT)];
            __nv_bfloat16 h = __float2bfloat16(w);
            __nv_bfloat16 l = __float2bfloat16(w - __bfloat162float(h));
            Whi[k * CP + n] = h;
            Wlo[k * CP + n] = l;
        }
        __syncthreads();

        // ---- one 16-k MMA step ----
        {
            wmma::fragment<wmma::matrix_a, 16, 16, 16, __nv_bfloat16,
                           wmma::row_major> ah0, ah1, al0, al1;
            wmma::load_matrix_sync(ah0, Ahi + (wm * 32) * KP, KP);
            wmma::load_matrix_sync(ah1, Ahi + (wm * 32 + 16) * KP, KP);
            wmma::load_matrix_sync(al0, Alo + (wm * 32) * KP, KP);
            wmma::load_matrix_sync(al1, Alo + (wm * 32 + 16) * KP, KP);
#pragma unroll
            for (int f = 0; f < NF; f++) {
                wmma::fragment<wmma::matrix_b, 16, 16, 16, __nv_bfloat16,
                               wmma::row_major> bh, bl;
                int ncol = wn * WN + f * 16;
                wmma::load_matrix_sync(bh, Whi + ncol, CP);
                wmma::load_matrix_sync(bl, Wlo + ncol, CP);
                wmma::mma_sync(acc[0][f], ah0, bh, acc[0][f]);
                wmma::mma_sync(acc[1][f], ah1, bh, acc[1][f]);
                wmma::mma_sync(acc[0][f], ah0, bl, acc[0][f]);
                wmma::mma_sync(acc[1][f], ah1, bl, acc[1][f]);
                wmma::mma_sync(acc[0][f], al0, bh, acc[0][f]);
                wmma::mma_sync(acc[1][f], al1, bh, acc[1][f]);
            }
        }
        __syncthreads();
    }

    // ---- epilogue: cols [0,COLT) -> g_t, [COLT,2*COLT) -> g_r ----
#pragma unroll
    for (int m = 0; m < 2; m++) {
        int r = rowBase + wm * 32 + m * 16;
#pragma unroll
        for (int f = 0; f < NF; f++) {
            int ncol = wn * WN + f * 16;
            float* Cout = (ncol < COLT) ? (g_t + (size_t)r * COLT + ncol)
                                        : (g_r + (size_t)r * COLT + (ncol - COLT));
            wmma::store_matrix_sync(Cout, acc[m][f], COLT, wmma::mem_row_major);
        }
    }
}

// ---------------- aggregation + combine -------------------------------------
template <int D, bool RELU>
__global__ __launch_bounds__(256)
void combine_kernel(const float* __restrict__ bias, float* __restrict__ outp) {
    int gw = (blockIdx.x * blockDim.x + threadIdx.x) >> 5;
    int lane = threadIdx.x & 31;
    if (gw >= NN) return;
    float* out = outp ? outp : g_h;

    int beg = g_rowoff[gw];
    int end = g_rowoff[gw + 1];

    if (D == 128) {
        float4 acc = make_float4(0.f, 0.f, 0.f, 0.f);
        const float* t = g_t;
        int j = beg;
        for (; j + 4 <= end; j += 4) {
            int s0 = g_csr[j], s1 = g_csr[j + 1], s2 = g_csr[j + 2], s3 = g_csr[j + 3];
            float4 v0 = *(const float4*)(t + (size_t)s0 * 128 + lane * 4);
            float4 v1 = *(const float4*)(t + (size_t)s1 * 128 + lane * 4);
            float4 v2 = *(const float4*)(t + (size_t)s2 * 128 + lane * 4);
            float4 v3 = *(const float4*)(t + (size_t)s3 * 128 + lane * 4);
            acc.x += v0.x + v1.x + v2.x + v3.x;
            acc.y += v0.y + v1.y + v2.y + v3.y;
            acc.z += v0.z + v1.z + v2.z + v3.z;
            acc.w += v0.w + v1.w + v2.w + v3.w;
        }
        for (; j < end; j++) {
            int s = g_csr[j];
            float4 v = *(const float4*)(t + (size_t)s * 128 + lane * 4);
            acc.x += v.x; acc.y += v.y; acc.z += v.z; acc.w += v.w;
        }
        float inv = g_invdeg[gw];
        float4 rr = *(const float4*)(g_r + (size_t)gw * 128 + lane * 4);
        float4 o;
        o.x = acc.x * inv + bias[lane * 4 + 0] + rr.x;
        o.y = acc.y * inv + bias[lane * 4 + 1] + rr.y;
        o.z = acc.z * inv + bias[lane * 4 + 2] + rr.z;
        o.w = acc.w * inv + bias[lane * 4 + 3] + rr.w;
        if (RELU) {
            o.x = fmaxf(o.x, 0.f); o.y = fmaxf(o.y, 0.f);
            o.z = fmaxf(o.z, 0.f); o.w = fmaxf(o.w, 0.f);
        }
        *(float4*)(out + (size_t)gw * 128 + lane * 4) = o;
    } else {
        float2 acc = make_float2(0.f, 0.f);
        const float* t = g_t;
        int j = beg;
        for (; j + 4 <= end; j += 4) {
            int s0 = g_csr[j], s1 = g_csr[j + 1], s2 = g_csr[j + 2], s3 = g_csr[j + 3];
            float2 v0 = *(const float2*)(t + (size_t)s0 * 64 + lane * 2);
            float2 v1 = *(const float2*)(t + (size_t)s1 * 64 + lane * 2);
            float2 v2 = *(const float2*)(t + (size_t)s2 * 64 + lane * 2);
            float2 v3 = *(const float2*)(t + (size_t)s3 * 64 + lane * 2);
            acc.x += v0.x + v1.x + v2.x + v3.x;
            acc.y += v0.y + v1.y + v2.y + v3.y;
        }
        for (; j < end; j++) {
            int s = g_csr[j];
            float2 v = *(const float2*)(t + (size_t)s * 64 + lane * 2);
            acc.x += v.x; acc.y += v.y;
        }
        float inv = g_invdeg[gw];
        float2 rr = *(const float2*)(g_r + (size_t)gw * 64 + lane * 2);
        float2 o;
        o.x = acc.x * inv + bias[lane * 2 + 0] + rr.x;
        o.y = acc.y * inv + bias[lane * 2 + 1] + rr.y;
        if (RELU) { o.x = fmaxf(o.x, 0.f); o.y = fmaxf(o.y, 0.f); }
        *(float2*)(out + (size_t)gw * 64 + lane * 2) = o;
    }
}

// ---------------- launch ------------------------------------------------------
extern "C" void kernel_launch(void* const* d_in, const int* in_sizes, int n_in,
                              void* d_out, int out_size) {
    const float* x    = (const float*)d_in[0];
    const void*  ei   = d_in[1];
    const float* w_l0 = (const float*)d_in[2];
    const float* b0   = (const float*)d_in[3];
    const float* w_r0 = (const float*)d_in[4];
    const float* w_l1 = (const float*)d_in[5];
    const float* b1   = (const float*)d_in[6];
    const float* w_r1 = (const float*)d_in[7];
    const float* w_l2 = (const float*)d_in[8];
    const float* b2   = (const float*)d_in[9];
    const float* w_r2 = (const float*)d_in[10];
    float* outp = (float*)d_out;

    const int gemmBlocks = (NN + 127) / 128;      // 391
    const int combBlocks = (NN * 32 + 255) / 256; // 6250

    count_deg_kernel<<<(EE + 255) / 256, 256>>>(ei);
    blocksum_kernel<<<NBLK, 256>>>();
    scan_bsum_kernel<<<1, 256>>>();
    gemm_wmma_kernel<128><<<gemmBlocks, 512>>>(x, w_l0, w_r0);   // profiled slot
    write_off_kernel<<<NBLK, 256>>>();
    fill_csr_kernel<<<(EE + 255) / 256, 256>>>(ei);
    combine_kernel<128, true><<<combBlocks, 256>>>(b0, nullptr);
    gemm_wmma_kernel<128><<<gemmBlocks, 512>>>(nullptr, w_l1, w_r1);
    combine_kernel<128, true><<<combBlocks, 256>>>(b1, nullptr);
    gemm_wmma_kernel<64><<<gemmBlocks, 512>>>(nullptr, w_l2, w_r2);
    combine_kernel<64, false><<<combBlocks, 256>>>(b2, outp);
}